// round 14
// baseline (speedup 1.0000x reference)
#include <cuda_runtime.h>
#include <math.h>
#include <stdint.h>

#define B_  4
#define L_  2048
#define H_  2048
#define NH_ 16
#define HD_ 128
#define M_  (B_ * L_)      // 8192
#define N3_ (3 * H_)       // 6144

// ---------------- scratch (device globals: only legal scratch) ----------------
__device__ float g_qkv[(size_t)M_ * N3_];
__device__ float g_Q[(size_t)B_ * NH_ * L_ * HD_];
__device__ float g_K[(size_t)B_ * NH_ * 32 * 8192];   // fragment-major
__device__ float g_V[(size_t)B_ * NH_ * 32 * 8192];   // fragment-major
__device__ float g_Y[(size_t)M_ * H_];
__device__ float g_X[(size_t)M_ * H_];                // tf32-rounded x
__device__ float g_Wq[(size_t)H_ * N3_];              // tf32-rounded Wqkv
__device__ float g_Wf[(size_t)H_ * H_];               // tf32-rounded Wfc2

__device__ __forceinline__ uint32_t f2tf32(float x) {
    uint32_t r;
    asm("cvt.rna.tf32.f32 %0, %1;" : "=r"(r) : "f"(x));
    return r;
}
__device__ __forceinline__ float rnd_tf32(float x) {
    return __uint_as_float(f2tf32(x));
}

__device__ __forceinline__ void mma_tf32(float c[4], const uint32_t a[4], const uint32_t b[2]) {
    asm volatile(
        "mma.sync.aligned.m16n8k8.row.col.f32.tf32.tf32.f32 "
        "{%0,%1,%2,%3}, {%4,%5,%6,%7}, {%8,%9}, {%0,%1,%2,%3};\n"
        : "+f"(c[0]), "+f"(c[1]), "+f"(c[2]), "+f"(c[3])
        : "r"(a[0]), "r"(a[1]), "r"(a[2]), "r"(a[3]), "r"(b[0]), "r"(b[1]));
}

// ---------------- elementwise tf32 rounding (vectorized) ----------------------
__global__ void round_tf32_kernel(const float4* __restrict__ in,
                                  float4* __restrict__ out, int n4)
{
    int i = blockIdx.x * blockDim.x + threadIdx.x;
    if (i < n4) {
        float4 v = in[i];
        v.x = rnd_tf32(v.x); v.y = rnd_tf32(v.y);
        v.z = rnd_tf32(v.z); v.w = rnd_tf32(v.w);
        out[i] = v;
    }
}

// ================= tf32 GEMM v4: 16 warps, 4 warps/SMSP =======================
// CTA tile 256x128 (same smem/L2 traffic as R9 best), BK=32.
// 512 threads = 16 warps in 4m x 4n grid, warp tile 64x32 -> acc 64 regs.
// ~115 regs/thread: whole CTA fits the RF with 4 warps per scheduler.
#define BM   256
#define BN   128
#define BKK  32
#define ASTR 36
#define BSTR 132
#define AWORDS (BM * ASTR)
#define BWORDS (BKK * BSTR)
#define GEMM_SMEM ((2 * AWORDS + 2 * BWORDS) * (int)sizeof(float))  // 107520

__global__ __launch_bounds__(512, 1) void gemm_tf32_v4(
    const float* __restrict__ A, const float* __restrict__ W,
    const float* __restrict__ bias, float* __restrict__ C,
    int M, int N, int K, int act)
{
    extern __shared__ float smem[];
    float* sA[2] = { smem, smem + AWORDS };
    float* sB[2] = { smem + 2 * AWORDS, smem + 2 * AWORDS + BWORDS };

    const int tid  = threadIdx.x;
    const int wid  = tid >> 5, lane = tid & 31;
    const int g    = lane >> 2, tg = lane & 3;
    const int wm   = (wid & 3) * 64;     // 4 m-warps
    const int wn   = (wid >> 2) * 32;    // 4 n-warps
    const int row0 = blockIdx.y * BM, col0 = blockIdx.x * BN;

    float acc[4][4][4];
#pragma unroll
    for (int i = 0; i < 4; i++)
#pragma unroll
        for (int j = 0; j < 4; j++)
#pragma unroll
            for (int r = 0; r < 4; r++) acc[i][j][r] = 0.f;

    auto loadTile = [&](int buf, int k0) {
        uint32_t sa = (uint32_t)__cvta_generic_to_shared(sA[buf]);
#pragma unroll
        for (int t = 0; t < 4; t++) {            // A: 256 rows x 8 float4
            int idx = t * 512 + tid;
            int r = idx >> 3, c = idx & 7;
            const float* src = A + (size_t)(row0 + r) * K + k0 + c * 4;
            asm volatile("cp.async.cg.shared.global [%0], [%1], 16;\n"
                         :: "r"(sa + (uint32_t)(r * ASTR + c * 4) * 4u), "l"(src));
        }
        uint32_t sb = (uint32_t)__cvta_generic_to_shared(sB[buf]);
#pragma unroll
        for (int t = 0; t < 2; t++) {            // B: 32 rows x 32 float4
            int idx = t * 512 + tid;
            int r = idx >> 5, c = idx & 31;
            const float* src = W + (size_t)(k0 + r) * N + col0 + c * 4;
            asm volatile("cp.async.cg.shared.global [%0], [%1], 16;\n"
                         :: "r"(sb + (uint32_t)(r * BSTR + c * 4) * 4u), "l"(src));
        }
    };

    auto compute = [&](int buf) {
        const float* sa = sA[buf];
        const float* sb = sB[buf];
#pragma unroll
        for (int kc = 0; kc < 4; kc++) {
            const int cA = kc * 8 + tg;
            uint32_t af[4][4], bf[4][2];
#pragma unroll
            for (int i = 0; i < 4; i++) {
                int rb = wm + i * 16;
                af[i][0] = __float_as_uint(sa[(rb + g) * ASTR + cA]);
                af[i][1] = __float_as_uint(sa[(rb + g + 8) * ASTR + cA]);
                af[i][2] = __float_as_uint(sa[(rb + g) * ASTR + cA + 4]);
                af[i][3] = __float_as_uint(sa[(rb + g + 8) * ASTR + cA + 4]);
            }
#pragma unroll
            for (int j = 0; j < 4; j++) {
                int cb = wn + j * 8 + g;
                bf[j][0] = __float_as_uint(sb[(kc * 8 + tg) * BSTR + cb]);
                bf[j][1] = __float_as_uint(sb[(kc * 8 + tg + 4) * BSTR + cb]);
            }
#pragma unroll
            for (int i = 0; i < 4; i++)
#pragma unroll
                for (int j = 0; j < 4; j++)
                    mma_tf32(acc[i][j], af[i], bf[j]);
        }
    };

    const int nIter = K / BKK;
    loadTile(0, 0);
    asm volatile("cp.async.commit_group;\n");
    for (int it = 0; it < nIter; it++) {
        asm volatile("cp.async.wait_group 0;\n");
        __syncthreads();
        if (it + 1 < nIter) {
            loadTile((it + 1) & 1, (it + 1) * BKK);
            asm volatile("cp.async.commit_group;\n");
        }
        compute(it & 1);
    }

#pragma unroll
    for (int i = 0; i < 4; i++) {
        int r = row0 + wm + i * 16 + g;
#pragma unroll
        for (int j = 0; j < 4; j++) {
            int c = col0 + wn + j * 8 + tg * 2;
            float b0 = bias[c], b1 = bias[c + 1];
            float v0 = acc[i][j][0] + b0;
            float v1 = acc[i][j][1] + b1;
            float v2 = acc[i][j][2] + b0;
            float v3 = acc[i][j][3] + b1;
            if (act) {
                v0 = v0 / (1.0f + expf(-v0));
                v1 = v1 / (1.0f + expf(-v1));
                v2 = v2 / (1.0f + expf(-v2));
                v3 = v3 / (1.0f + expf(-v3));
            }
            *(float2*)&C[(size_t)r * N + c] = make_float2(v0, v1);
            *(float2*)&C[(size_t)(r + 8) * N + c] = make_float2(v2, v3);
        }
    }
}

// ---------------- RoPE + scatter (Q row-major; K/V fragment-major) ------------
__global__ void rope_scatter(const float* __restrict__ qkv,
                             const float* __restrict__ cosb,
                             const float* __restrict__ sinb,
                             float* __restrict__ Q, float* __restrict__ K,
                             float* __restrict__ V)
{
    __shared__ float sh[N3_];
    const int bt = blockIdx.x;
    const int b = bt >> 11, t = bt & 2047;
    const float scale = 0.08838834764831843f;
    const float* row = qkv + (size_t)bt * N3_;
    for (int i = threadIdx.x; i < N3_; i += blockDim.x) sh[i] = row[i];
    __syncthreads();

    const int tile = t >> 6, r = t & 63;
    const int Kn = r >> 3, Kg = r & 7;
    const int Vkc = r >> 3, Vtg = r & 3, Vdlt = (r >> 2) & 1;

    for (int i = threadIdx.x; i < 1024; i += blockDim.x) {
        int h = i >> 6;
        int d = i & 63;
        int e1 = d * 16 + h;
        float c = cosb[(size_t)t * 1024 + e1];
        float s = sinb[(size_t)t * 1024 + e1];
        const int bh = b * NH_ + h;

        float u1 = sh[e1], u2 = sh[e1 + 1024];
        size_t qbase = ((size_t)bh * L_ + t) * HD_;
        Q[qbase + d]      = rnd_tf32(( u1 * c + u2 * s) * scale);
        Q[qbase + d + 64] = rnd_tf32((-u1 * s + u2 * c) * scale);

        u1 = sh[H_ + e1]; u2 = sh[H_ + e1 + 1024];
        float k0 = rnd_tf32( u1 * c + u2 * s);
        float k1 = rnd_tf32(-u1 * s + u2 * c);
        size_t kbase = ((size_t)bh * 32 + tile) * 8192;
        int kc = d >> 3, tg = d & 3, dlt = (d >> 2) & 1;
        K[kbase + (size_t)(((Kn * 16 + kc) * 32 + Kg * 4 + tg) * 2 + dlt)]     = k0;
        K[kbase + (size_t)(((Kn * 16 + kc + 8) * 32 + Kg * 4 + tg) * 2 + dlt)] = k1;
    }
    for (int i = threadIdx.x; i < H_; i += blockDim.x) {
        int h = i >> 7, dd = i & 127;
        int n = dd >> 3, g = dd & 7;
        size_t vbase = (((size_t)(b * NH_ + h)) * 32 + tile) * 8192;
        V[vbase + (size_t)(((Vkc * 16 + n) * 32 + Vtg * 8 + g) * 2 + Vdlt)] =
            rnd_tf32(sh[2 * H_ + dd * 16 + h]);
    }
}

// ================= flash attention v3 (unchanged) =============================
#define QSTR 132
#define QWORDS (128 * QSTR)
#define ATTN_SMEM ((QWORDS + 4 * 8192) * (int)sizeof(float))

__global__ __launch_bounds__(256, 1) void attn_tc3(
    const float* __restrict__ Q, const float* __restrict__ K,
    const float* __restrict__ V, float* __restrict__ Y)
{
    extern __shared__ float smem[];
    float* sQ = smem;
    float* sKb[2] = { smem + QWORDS, smem + QWORDS + 8192 };
    float* sVb[2] = { smem + QWORDS + 2 * 8192, smem + QWORDS + 3 * 8192 };

    const int tid  = threadIdx.x;
    const int wid  = tid >> 5, lane = tid & 31;
    const int g    = lane >> 2, tg = lane & 3;
    const int wm   = wid * 16;
    const int qt   = 15 - (int)blockIdx.x;
    const int bh   = blockIdx.y;

    const float* Qg = Q + (size_t)bh * L_ * HD_ + (size_t)qt * 128 * HD_;
    const float* Kg = K + (size_t)bh * 32 * 8192;
    const float* Vg = V + (size_t)bh * 32 * 8192;

    auto loadKV = [&](int buf, int kt2) {
        const float* Kp = Kg + (size_t)kt2 * 8192;
        const float* Vp = Vg + (size_t)kt2 * 8192;
        uint32_t sk = (uint32_t)__cvta_generic_to_shared(sKb[buf]);
        uint32_t sv = (uint32_t)__cvta_generic_to_shared(sVb[buf]);
#pragma unroll
        for (int t = 0; t < 8; t++) {
            int w4 = (t * 256 + tid) * 4;
            asm volatile("cp.async.cg.shared.global [%0], [%1], 16;\n"
                         :: "r"(sk + (uint32_t)w4 * 4u), "l"(Kp + w4));
            asm volatile("cp.async.cg.shared.global [%0], [%1], 16;\n"
                         :: "r"(sv + (uint32_t)w4 * 4u), "l"(Vp + w4));
        }
    };

    {
        uint32_t sq = (uint32_t)__cvta_generic_to_shared(sQ);
#pragma unroll
        for (int t = 0; t < 16; t++) {
            int idx = t * 256 + tid;
            int r = idx >> 5, c = idx & 31;
            asm volatile("cp.async.cg.shared.global [%0], [%1], 16;\n"
                         :: "r"(sq + (uint32_t)(r * QSTR + c * 4) * 4u),
                            "l"(Qg + r * HD_ + c * 4));
        }
    }
    loadKV(0, 0);
    asm volatile("cp.async.commit_group;\n");
    asm volatile("cp.async.wait_group 0;\n");
    __syncthreads();

    uint32_t qf[16][4];
#pragma unroll
    for (int kc = 0; kc < 16; kc++) {
        const int ka = kc * 8 + tg;
        qf[kc][0] = __float_as_uint(sQ[(wm + g) * QSTR + ka]);
        qf[kc][1] = __float_as_uint(sQ[(wm + g + 8) * QSTR + ka]);
        qf[kc][2] = __float_as_uint(sQ[(wm + g) * QSTR + ka + 4]);
        qf[kc][3] = __float_as_uint(sQ[(wm + g + 8) * QSTR + ka + 4]);
    }

    float of[16][4];
#pragma unroll
    for (int n = 0; n < 16; n++)
#pragma unroll
        for (int r = 0; r < 4; r++) of[n][r] = 0.f;
    float m0 = -1e30f, m1 = -1e30f, l0 = 0.f, l1 = 0.f;

    const int nt = 2 * qt + 2;

    for (int kt = 0; kt < nt; kt++) {
        const int buf = kt & 1;
        if (kt + 1 < nt) {
            loadKV(buf ^ 1, kt + 1);
            asm volatile("cp.async.commit_group;\n");
            asm volatile("cp.async.wait_group 1;\n");
        } else {
            asm volatile("cp.async.wait_group 0;\n");
        }
        __syncthreads();

        const int rowmin = qt * 128 + wm;
        const bool fullM = (kt * 64 > rowmin + 15);
        if (!fullM) {
            const float2* sK2 = (const float2*)sKb[buf];
            const float2* sV2 = (const float2*)sVb[buf];
            const int kOff = g * 4 + tg;
            const int vOff = tg * 8 + g;

            float sacc[8][4];
#pragma unroll
            for (int n = 0; n < 8; n++)
#pragma unroll
                for (int r = 0; r < 4; r++) sacc[n][r] = 0.f;

#pragma unroll
            for (int kc = 0; kc < 16; kc++) {
#pragma unroll
                for (int n = 0; n < 8; n++) {
                    float2 kv = sK2[(n * 16 + kc) * 32 + kOff];
                    uint32_t bf[2] = { __float_as_uint(kv.x), __float_as_uint(kv.y) };
                    mma_tf32(sacc[n], qf[kc], bf);
                }
            }

            if (kt * 64 + 63 > rowmin) {
                const int r0 = rowmin + g, r1 = r0 + 8;
#pragma unroll
                for (int n = 0; n < 8; n++) {
                    int c0 = kt * 64 + 8 * n + 2 * tg;
                    if (c0 > r0)     sacc[n][0] = -1e30f;
                    if (c0 + 1 > r0) sacc[n][1] = -1e30f;
                    if (c0 > r1)     sacc[n][2] = -1e30f;
                    if (c0 + 1 > r1) sacc[n][3] = -1e30f;
                }
            }

            float vx0 = -1e30f, vx1 = -1e30f;
#pragma unroll
            for (int n = 0; n < 8; n++) {
                vx0 = fmaxf(vx0, fmaxf(sacc[n][0], sacc[n][1]));
                vx1 = fmaxf(vx1, fmaxf(sacc[n][2], sacc[n][3]));
            }
            vx0 = fmaxf(vx0, __shfl_xor_sync(0xffffffffu, vx0, 1));
            vx0 = fmaxf(vx0, __shfl_xor_sync(0xffffffffu, vx0, 2));
            vx1 = fmaxf(vx1, __shfl_xor_sync(0xffffffffu, vx1, 1));
            vx1 = fmaxf(vx1, __shfl_xor_sync(0xffffffffu, vx1, 2));

            const float mn0 = fmaxf(m0, vx0), mn1 = fmaxf(m1, vx1);
            const float a0 = __expf(m0 - mn0), a1 = __expf(m1 - mn1);
            m0 = mn0; m1 = mn1;

            float s0 = 0.f, s1 = 0.f;
#pragma unroll
            for (int n = 0; n < 8; n++) {
                float p0 = __expf(sacc[n][0] - mn0);
                float p1 = __expf(sacc[n][1] - mn0);
                float p2 = __expf(sacc[n][2] - mn1);
                float p3 = __expf(sacc[n][3] - mn1);
                s0 += p0 + p1; s1 += p2 + p3;
                sacc[n][0] = __uint_as_float(f2tf32(p0));
                sacc[n][1] = __uint_as_float(f2tf32(p1));
                sacc[n][2] = __uint_as_float(f2tf32(p2));
                sacc[n][3] = __uint_as_float(f2tf32(p3));
            }
            s0 += __shfl_xor_sync(0xffffffffu, s0, 1);
            s0 += __shfl_xor_sync(0xffffffffu, s0, 2);
            s1 += __shfl_xor_sync(0xffffffffu, s1, 1);
            s1 += __shfl_xor_sync(0xffffffffu, s1, 2);
            l0 = l0 * a0 + s0;
            l1 = l1 * a1 + s1;

#pragma unroll
            for (int n = 0; n < 16; n++) {
                of[n][0] *= a0; of[n][1] *= a0;
                of[n][2] *= a1; of[n][3] *= a1;
            }

            const int base = lane & ~3;
            const int hsrc = base + (tg >> 1);
            const bool par = (tg & 1);
#pragma unroll
            for (int kc = 0; kc < 8; kc++) {
                uint32_t a[4];
                {
                    float lo = __shfl_sync(0xffffffffu, sacc[kc][0], hsrc);
                    float hi = __shfl_sync(0xffffffffu, sacc[kc][1], hsrc);
                    a[0] = __float_as_uint(par ? hi : lo);
                    lo = __shfl_sync(0xffffffffu, sacc[kc][2], hsrc);
                    hi = __shfl_sync(0xffffffffu, sacc[kc][3], hsrc);
                    a[1] = __float_as_uint(par ? hi : lo);
                    lo = __shfl_sync(0xffffffffu, sacc[kc][0], hsrc + 2);
                    hi = __shfl_sync(0xffffffffu, sacc[kc][1], hsrc + 2);
                    a[2] = __float_as_uint(par ? hi : lo);
                    lo = __shfl_sync(0xffffffffu, sacc[kc][2], hsrc + 2);
                    hi = __shfl_sync(0xffffffffu, sacc[kc][3], hsrc + 2);
                    a[3] = __float_as_uint(par ? hi : lo);
                }
#pragma unroll
                for (int n = 0; n < 16; n++) {
                    float2 vv = sV2[(kc * 16 + n) * 32 + vOff];
                    uint32_t bf[2] = { __float_as_uint(vv.x), __float_as_uint(vv.y) };
                    mma_tf32(of[n], a, bf);
                }
            }
        }
        __syncthreads();
    }

    const int b = bh >> 4, h = bh & 15;
    const float inv0 = 1.0f / l0;
    const float inv1 = 1.0f / l1;
    const int t0 = qt * 128 + wm + g;
    const int t1 = t0 + 8;
#pragma unroll
    for (int n = 0; n < 16; n++) {
        int d = 8 * n + 2 * tg;
        *(float2*)&Y[((size_t)(b * L_ + t0)) * H_ + h * HD_ + d] =
            make_float2(rnd_tf32(of[n][0] * inv0), rnd_tf32(of[n][1] * inv0));
        *(float2*)&Y[((size_t)(b * L_ + t1)) * H_ + h * HD_ + d] =
            make_float2(rnd_tf32(of[n][2] * inv1), rnd_tf32(of[n][3] * inv1));
    }
}

// ---------------- launcher ----------------------------------------------------
extern "C" void kernel_launch(void* const* d_in, const int* in_sizes, int n_in,
                              void* d_out, int out_size)
{
    const float* x    = (const float*)d_in[0];
    const float* Wqkv = (const float*)d_in[1];
    const float* bqkv = (const float*)d_in[2];
    const float* Wfc2 = (const float*)d_in[3];
    const float* bfc2 = (const float*)d_in[4];
    const float* cosb = (const float*)d_in[5];
    const float* sinb = (const float*)d_in[6];
    float* out = (float*)d_out;

    float *qkv, *Qh, *Kh, *Vh, *Yb, *Xr, *Wqr, *Wfr;
    cudaGetSymbolAddress((void**)&qkv, g_qkv);
    cudaGetSymbolAddress((void**)&Qh,  g_Q);
    cudaGetSymbolAddress((void**)&Kh,  g_K);
    cudaGetSymbolAddress((void**)&Vh,  g_V);
    cudaGetSymbolAddress((void**)&Yb,  g_Y);
    cudaGetSymbolAddress((void**)&Xr,  g_X);
    cudaGetSymbolAddress((void**)&Wqr, g_Wq);
    cudaGetSymbolAddress((void**)&Wfr, g_Wf);

    cudaFuncSetAttribute(gemm_tf32_v4, cudaFuncAttributeMaxDynamicSharedMemorySize, GEMM_SMEM);
    cudaFuncSetAttribute(attn_tc3, cudaFuncAttributeMaxDynamicSharedMemorySize, ATTN_SMEM);

    // 0) pre-round operands to tf32
    {
        int n4x = (int)((size_t)M_ * H_ / 4);
        int n4q = (int)((size_t)H_ * N3_ / 4);
        int n4f = (int)((size_t)H_ * H_ / 4);
        round_tf32_kernel<<<(n4x + 255) / 256, 256>>>((const float4*)x,    (float4*)Xr,  n4x);
        round_tf32_kernel<<<(n4q + 255) / 256, 256>>>((const float4*)Wqkv, (float4*)Wqr, n4q);
        round_tf32_kernel<<<(n4f + 255) / 256, 256>>>((const float4*)Wfc2, (float4*)Wfr, n4f);
    }

    // 1) QKV GEMM
    gemm_tf32_v4<<<dim3(N3_ / BN, M_ / BM), 512, GEMM_SMEM>>>(Xr, Wqr, bqkv, qkv, M_, N3_, H_, 0);

    // 2) RoPE + scatter
    rope_scatter<<<M_, 256>>>(qkv, cosb, sinb, Qh, Kh, Vh);

    // 3) causal flash attention
    attn_tc3<<<dim3(L_ / 128, B_ * NH_), 256, ATTN_SMEM>>>(Qh, Kh, Vh, Yb);

    // 4) FC2 GEMM + SiLU
    gemm_tf32_v4<<<dim3(H_ / BN, M_ / BM), 512, GEMM_SMEM>>>(Yb, Wfr, bfc2, out, M_, H_, H_, 1);
}

// round 16
// speedup vs baseline: 1.5341x; 1.5341x over previous
#include <cuda_runtime.h>
#include <cuda_fp16.h>
#include <math.h>
#include <stdint.h>

#define B_  4
#define L_  2048
#define H_  2048
#define NH_ 16
#define HD_ 128
#define M_  (B_ * L_)      // 8192
#define N3_ (3 * H_)       // 6144

// ---------------- scratch (device globals: only legal scratch) ----------------
__device__ float  g_qkv[(size_t)M_ * N3_];
__device__ float  g_Q[(size_t)B_ * NH_ * L_ * HD_];
__device__ float  g_K[(size_t)B_ * NH_ * 32 * 8192];   // fragment-major
__device__ float  g_V[(size_t)B_ * NH_ * 32 * 8192];   // fragment-major
__device__ __half g_Xh[(size_t)M_ * H_];               // fp16 x
__device__ __half g_WqTh[(size_t)H_ * N3_];            // fp16 Wqkv^T [6144][2048]
__device__ __half g_WfTh[(size_t)H_ * H_];             // fp16 Wfc2^T [2048][2048]
__device__ __half g_Yh[(size_t)M_ * H_];               // fp16 attention output

__device__ __forceinline__ uint32_t f2tf32(float x) {
    uint32_t r;
    asm("cvt.rna.tf32.f32 %0, %1;" : "=r"(r) : "f"(x));
    return r;
}
__device__ __forceinline__ float rnd_tf32(float x) {
    return __uint_as_float(f2tf32(x));
}

__device__ __forceinline__ void mma_tf32(float c[4], const uint32_t a[4], const uint32_t b[2]) {
    asm volatile(
        "mma.sync.aligned.m16n8k8.row.col.f32.tf32.tf32.f32 "
        "{%0,%1,%2,%3}, {%4,%5,%6,%7}, {%8,%9}, {%0,%1,%2,%3};\n"
        : "+f"(c[0]), "+f"(c[1]), "+f"(c[2]), "+f"(c[3])
        : "r"(a[0]), "r"(a[1]), "r"(a[2]), "r"(a[3]), "r"(b[0]), "r"(b[1]));
}

__device__ __forceinline__ void mma_f16(float c[4], const uint32_t a[4], const uint32_t b[2]) {
    asm volatile(
        "mma.sync.aligned.m16n8k16.row.col.f32.f16.f16.f32 "
        "{%0,%1,%2,%3}, {%4,%5,%6,%7}, {%8,%9}, {%0,%1,%2,%3};\n"
        : "+f"(c[0]), "+f"(c[1]), "+f"(c[2]), "+f"(c[3])
        : "r"(a[0]), "r"(a[1]), "r"(a[2]), "r"(a[3]), "r"(b[0]), "r"(b[1]));
}

// ---------------- fp32 -> fp16 conversion (vectorized) ------------------------
__global__ void f32_to_f16(const float4* __restrict__ in, uint2* __restrict__ out, int n4)
{
    int i = blockIdx.x * blockDim.x + threadIdx.x;
    if (i < n4) {
        float4 v = in[i];
        __half2 h0 = __floats2half2_rn(v.x, v.y);
        __half2 h1 = __floats2half2_rn(v.z, v.w);
        uint2 o;
        o.x = *(uint32_t*)&h0;
        o.y = *(uint32_t*)&h1;
        out[i] = o;
    }
}

// ---------------- transpose + fp16: out[c][r] = f16(in[r][c]) -----------------
__global__ void transpose_f16(const float* __restrict__ in, __half* __restrict__ out,
                              int R, int Ccols)
{
    __shared__ float t[32][33];
    int r0 = blockIdx.y * 32, c0 = blockIdx.x * 32;
    int tx = threadIdx.x & 31, ty = threadIdx.x >> 5;
    for (int i = ty; i < 32; i += 8)
        t[i][tx] = in[(size_t)(r0 + i) * Ccols + c0 + tx];
    __syncthreads();
    for (int i = ty; i < 32; i += 8)
        out[(size_t)(c0 + i) * R + r0 + tx] = __float2half_rn(t[tx][i]);
}

// ================= fp16 tensor-core GEMM ======================================
// C[M,N] = Ah[M,K] @ BhT[N,K]^T + bias (opt SiLU), fp32 accumulate.
// CTA tile 256x128, BK=32, 8 warps (4m x 2n), warp tile 64x64.
// Smem rows: 16 data words (32 fp16) + 4 pad = RS 20 words -> conflict-free
// fragment loads (bank(g*20+tg) is a permutation over the warp).
#define FBM  256
#define FBN  128
#define FBK  32
#define FRS  20                              // words per smem row
#define FAW  (FBM * FRS)                     // 5120 words
#define FBW  (FBN * FRS)                     // 2560 words
#define FGEMM_SMEM ((2 * FAW + 2 * FBW) * 4) // 61440 B

__global__ __launch_bounds__(256) void gemm_f16(
    const __half* __restrict__ A, const __half* __restrict__ Bt,
    const float* __restrict__ bias, float* __restrict__ C,
    int M, int N, int K, int act)
{
    extern __shared__ uint32_t fsm[];
    uint32_t* sA[2] = { fsm, fsm + FAW };
    uint32_t* sB[2] = { fsm + 2 * FAW, fsm + 2 * FAW + FBW };

    const int tid  = threadIdx.x;
    const int wid  = tid >> 5, lane = tid & 31;
    const int g    = lane >> 2, tg = lane & 3;
    const int wm   = (wid & 3) * 64;
    const int wn   = (wid >> 2) * 64;
    const int row0 = blockIdx.y * FBM, col0 = blockIdx.x * FBN;

    float acc[4][8][4];
#pragma unroll
    for (int i = 0; i < 4; i++)
#pragma unroll
        for (int j = 0; j < 8; j++)
#pragma unroll
            for (int r = 0; r < 4; r++) acc[i][j][r] = 0.f;

    auto loadTile = [&](int buf, int k0) {
        uint32_t sa = (uint32_t)__cvta_generic_to_shared(sA[buf]);
#pragma unroll
        for (int t = 0; t < 4; t++) {          // A: 256 rows x 4 chunks of 16B
            int idx = t * 256 + tid;
            int r = idx >> 2, c = idx & 3;
            const __half* src = A + (size_t)(row0 + r) * K + k0 + c * 8;
            uint32_t dst = sa + (uint32_t)(r * FRS + c * 4) * 4u;
            asm volatile("cp.async.cg.shared.global [%0], [%1], 16;\n" :: "r"(dst), "l"(src));
        }
        uint32_t sb = (uint32_t)__cvta_generic_to_shared(sB[buf]);
#pragma unroll
        for (int t = 0; t < 2; t++) {          // B: 128 rows x 4 chunks of 16B
            int idx = t * 256 + tid;
            int r = idx >> 2, c = idx & 3;
            const __half* src = Bt + (size_t)(col0 + r) * K + k0 + c * 8;
            uint32_t dst = sb + (uint32_t)(r * FRS + c * 4) * 4u;
            asm volatile("cp.async.cg.shared.global [%0], [%1], 16;\n" :: "r"(dst), "l"(src));
        }
    };

    uint32_t af[2][4][4], bf[2][8][2];

    auto ldfrag = [&](const uint32_t* sa, const uint32_t* sb, int pb, int kc) {
        const int wbase = kc * 8 + tg;         // word index within row
#pragma unroll
        for (int i = 0; i < 4; i++) {
            int rb = wm + i * 16;
            af[pb][i][0] = sa[(rb + g) * FRS + wbase];
            af[pb][i][1] = sa[(rb + g + 8) * FRS + wbase];
            af[pb][i][2] = sa[(rb + g) * FRS + wbase + 4];
            af[pb][i][3] = sa[(rb + g + 8) * FRS + wbase + 4];
        }
#pragma unroll
        for (int j = 0; j < 8; j++) {
            int cb = wn + j * 8 + g;
            bf[pb][j][0] = sb[cb * FRS + wbase];
            bf[pb][j][1] = sb[cb * FRS + wbase + 4];
        }
    };

    const int nIter = K / FBK;
    loadTile(0, 0);
    asm volatile("cp.async.commit_group;\n");
    for (int it = 0; it < nIter; it++) {
        asm volatile("cp.async.wait_group 0;\n");
        __syncthreads();
        if (it + 1 < nIter) {
            loadTile((it + 1) & 1, (it + 1) * FBK);
            asm volatile("cp.async.commit_group;\n");
        }
        const uint32_t* sa = sA[it & 1];
        const uint32_t* sb = sB[it & 1];
        ldfrag(sa, sb, 0, 0);
#pragma unroll
        for (int kc = 0; kc < 2; kc++) {       // two k16 steps per 32-K chunk
            const int cur = kc & 1;
            if (kc < 1) ldfrag(sa, sb, cur ^ 1, kc + 1);
#pragma unroll
            for (int i = 0; i < 4; i++)
#pragma unroll
                for (int j = 0; j < 8; j++)
                    mma_f16(acc[i][j], af[cur][i], bf[cur][j]);
        }
    }

#pragma unroll
    for (int i = 0; i < 4; i++) {
        int r = row0 + wm + i * 16 + g;
#pragma unroll
        for (int j = 0; j < 8; j++) {
            int c = col0 + wn + j * 8 + tg * 2;
            float b0 = bias[c], b1 = bias[c + 1];
            float v0 = acc[i][j][0] + b0;
            float v1 = acc[i][j][1] + b1;
            float v2 = acc[i][j][2] + b0;
            float v3 = acc[i][j][3] + b1;
            if (act) {
                v0 = v0 / (1.0f + expf(-v0));
                v1 = v1 / (1.0f + expf(-v1));
                v2 = v2 / (1.0f + expf(-v2));
                v3 = v3 / (1.0f + expf(-v3));
            }
            *(float2*)&C[(size_t)r * N + c] = make_float2(v0, v1);
            *(float2*)&C[(size_t)(r + 8) * N + c] = make_float2(v2, v3);
        }
    }
}

// ---------------- RoPE + scatter (Q row-major; K/V fragment-major) ------------
__global__ void rope_scatter(const float* __restrict__ qkv,
                             const float* __restrict__ cosb,
                             const float* __restrict__ sinb,
                             float* __restrict__ Q, float* __restrict__ K,
                             float* __restrict__ V)
{
    __shared__ float sh[N3_];
    const int bt = blockIdx.x;
    const int b = bt >> 11, t = bt & 2047;
    const float scale = 0.08838834764831843f;
    const float* row = qkv + (size_t)bt * N3_;
    for (int i = threadIdx.x; i < N3_; i += blockDim.x) sh[i] = row[i];
    __syncthreads();

    const int tile = t >> 6, r = t & 63;
    const int Kn = r >> 3, Kg = r & 7;
    const int Vkc = r >> 3, Vtg = r & 3, Vdlt = (r >> 2) & 1;

    for (int i = threadIdx.x; i < 1024; i += blockDim.x) {
        int h = i >> 6;
        int d = i & 63;
        int e1 = d * 16 + h;
        float c = cosb[(size_t)t * 1024 + e1];
        float s = sinb[(size_t)t * 1024 + e1];
        const int bh = b * NH_ + h;

        float u1 = sh[e1], u2 = sh[e1 + 1024];
        size_t qbase = ((size_t)bh * L_ + t) * HD_;
        Q[qbase + d]      = rnd_tf32(( u1 * c + u2 * s) * scale);
        Q[qbase + d + 64] = rnd_tf32((-u1 * s + u2 * c) * scale);

        u1 = sh[H_ + e1]; u2 = sh[H_ + e1 + 1024];
        float k0 = rnd_tf32( u1 * c + u2 * s);
        float k1 = rnd_tf32(-u1 * s + u2 * c);
        size_t kbase = ((size_t)bh * 32 + tile) * 8192;
        int kc = d >> 3, tg = d & 3, dlt = (d >> 2) & 1;
        K[kbase + (size_t)(((Kn * 16 + kc) * 32 + Kg * 4 + tg) * 2 + dlt)]     = k0;
        K[kbase + (size_t)(((Kn * 16 + kc + 8) * 32 + Kg * 4 + tg) * 2 + dlt)] = k1;
    }
    for (int i = threadIdx.x; i < H_; i += blockDim.x) {
        int h = i >> 7, dd = i & 127;
        int n = dd >> 3, g = dd & 7;
        size_t vbase = (((size_t)(b * NH_ + h)) * 32 + tile) * 8192;
        V[vbase + (size_t)(((Vkc * 16 + n) * 32 + Vtg * 8 + g) * 2 + Vdlt)] =
            rnd_tf32(sh[2 * H_ + dd * 16 + h]);
    }
}

// ================= flash attention v3 (epilogue writes fp16 Y) ================
#define QSTR 132
#define QWORDS (128 * QSTR)
#define ATTN_SMEM ((QWORDS + 4 * 8192) * (int)sizeof(float))

__global__ __launch_bounds__(256, 1) void attn_tc3(
    const float* __restrict__ Q, const float* __restrict__ K,
    const float* __restrict__ V, __half* __restrict__ Y)
{
    extern __shared__ float smem[];
    float* sQ = smem;
    float* sKb[2] = { smem + QWORDS, smem + QWORDS + 8192 };
    float* sVb[2] = { smem + QWORDS + 2 * 8192, smem + QWORDS + 3 * 8192 };

    const int tid  = threadIdx.x;
    const int wid  = tid >> 5, lane = tid & 31;
    const int g    = lane >> 2, tg = lane & 3;
    const int wm   = wid * 16;
    const int qt   = 15 - (int)blockIdx.x;
    const int bh   = blockIdx.y;

    const float* Qg = Q + (size_t)bh * L_ * HD_ + (size_t)qt * 128 * HD_;
    const float* Kg = K + (size_t)bh * 32 * 8192;
    const float* Vg = V + (size_t)bh * 32 * 8192;

    auto loadKV = [&](int buf, int kt2) {
        const float* Kp = Kg + (size_t)kt2 * 8192;
        const float* Vp = Vg + (size_t)kt2 * 8192;
        uint32_t sk = (uint32_t)__cvta_generic_to_shared(sKb[buf]);
        uint32_t sv = (uint32_t)__cvta_generic_to_shared(sVb[buf]);
#pragma unroll
        for (int t = 0; t < 8; t++) {
            int w4 = (t * 256 + tid) * 4;
            asm volatile("cp.async.cg.shared.global [%0], [%1], 16;\n"
                         :: "r"(sk + (uint32_t)w4 * 4u), "l"(Kp + w4));
            asm volatile("cp.async.cg.shared.global [%0], [%1], 16;\n"
                         :: "r"(sv + (uint32_t)w4 * 4u), "l"(Vp + w4));
        }
    };

    {
        uint32_t sq = (uint32_t)__cvta_generic_to_shared(sQ);
#pragma unroll
        for (int t = 0; t < 16; t++) {
            int idx = t * 256 + tid;
            int r = idx >> 5, c = idx & 31;
            asm volatile("cp.async.cg.shared.global [%0], [%1], 16;\n"
                         :: "r"(sq + (uint32_t)(r * QSTR + c * 4) * 4u),
                            "l"(Qg + r * HD_ + c * 4));
        }
    }
    loadKV(0, 0);
    asm volatile("cp.async.commit_group;\n");
    asm volatile("cp.async.wait_group 0;\n");
    __syncthreads();

    uint32_t qf[16][4];
#pragma unroll
    for (int kc = 0; kc < 16; kc++) {
        const int ka = kc * 8 + tg;
        qf[kc][0] = __float_as_uint(sQ[(wm + g) * QSTR + ka]);
        qf[kc][1] = __float_as_uint(sQ[(wm + g + 8) * QSTR + ka]);
        qf[kc][2] = __float_as_uint(sQ[(wm + g) * QSTR + ka + 4]);
        qf[kc][3] = __float_as_uint(sQ[(wm + g + 8) * QSTR + ka + 4]);
    }

    float of[16][4];
#pragma unroll
    for (int n = 0; n < 16; n++)
#pragma unroll
        for (int r = 0; r < 4; r++) of[n][r] = 0.f;
    float m0 = -1e30f, m1 = -1e30f, l0 = 0.f, l1 = 0.f;

    const int nt = 2 * qt + 2;

    for (int kt = 0; kt < nt; kt++) {
        const int buf = kt & 1;
        if (kt + 1 < nt) {
            loadKV(buf ^ 1, kt + 1);
            asm volatile("cp.async.commit_group;\n");
            asm volatile("cp.async.wait_group 1;\n");
        } else {
            asm volatile("cp.async.wait_group 0;\n");
        }
        __syncthreads();

        const int rowmin = qt * 128 + wm;
        const bool fullM = (kt * 64 > rowmin + 15);
        if (!fullM) {
            const float2* sK2 = (const float2*)sKb[buf];
            const float2* sV2 = (const float2*)sVb[buf];
            const int kOff = g * 4 + tg;
            const int vOff = tg * 8 + g;

            float sacc[8][4];
#pragma unroll
            for (int n = 0; n < 8; n++)
#pragma unroll
                for (int r = 0; r < 4; r++) sacc[n][r] = 0.f;

#pragma unroll
            for (int kc = 0; kc < 16; kc++) {
#pragma unroll
                for (int n = 0; n < 8; n++) {
                    float2 kv = sK2[(n * 16 + kc) * 32 + kOff];
                    uint32_t bf[2] = { __float_as_uint(kv.x), __float_as_uint(kv.y) };
                    mma_tf32(sacc[n], qf[kc], bf);
                }
            }

            if (kt * 64 + 63 > rowmin) {
                const int r0 = rowmin + g, r1 = r0 + 8;
#pragma unroll
                for (int n = 0; n < 8; n++) {
                    int c0 = kt * 64 + 8 * n + 2 * tg;
                    if (c0 > r0)     sacc[n][0] = -1e30f;
                    if (c0 + 1 > r0) sacc[n][1] = -1e30f;
                    if (c0 > r1)     sacc[n][2] = -1e30f;
                    if (c0 + 1 > r1) sacc[n][3] = -1e30f;
                }
            }

            float vx0 = -1e30f, vx1 = -1e30f;
#pragma unroll
            for (int n = 0; n < 8; n++) {
                vx0 = fmaxf(vx0, fmaxf(sacc[n][0], sacc[n][1]));
                vx1 = fmaxf(vx1, fmaxf(sacc[n][2], sacc[n][3]));
            }
            vx0 = fmaxf(vx0, __shfl_xor_sync(0xffffffffu, vx0, 1));
            vx0 = fmaxf(vx0, __shfl_xor_sync(0xffffffffu, vx0, 2));
            vx1 = fmaxf(vx1, __shfl_xor_sync(0xffffffffu, vx1, 1));
            vx1 = fmaxf(vx1, __shfl_xor_sync(0xffffffffu, vx1, 2));

            const float mn0 = fmaxf(m0, vx0), mn1 = fmaxf(m1, vx1);
            const float a0 = __expf(m0 - mn0), a1 = __expf(m1 - mn1);
            m0 = mn0; m1 = mn1;

            float s0 = 0.f, s1 = 0.f;
#pragma unroll
            for (int n = 0; n < 8; n++) {
                float p0 = __expf(sacc[n][0] - mn0);
                float p1 = __expf(sacc[n][1] - mn0);
                float p2 = __expf(sacc[n][2] - mn1);
                float p3 = __expf(sacc[n][3] - mn1);
                s0 += p0 + p1; s1 += p2 + p3;
                sacc[n][0] = __uint_as_float(f2tf32(p0));
                sacc[n][1] = __uint_as_float(f2tf32(p1));
                sacc[n][2] = __uint_as_float(f2tf32(p2));
                sacc[n][3] = __uint_as_float(f2tf32(p3));
            }
            s0 += __shfl_xor_sync(0xffffffffu, s0, 1);
            s0 += __shfl_xor_sync(0xffffffffu, s0, 2);
            s1 += __shfl_xor_sync(0xffffffffu, s1, 1);
            s1 += __shfl_xor_sync(0xffffffffu, s1, 2);
            l0 = l0 * a0 + s0;
            l1 = l1 * a1 + s1;

#pragma unroll
            for (int n = 0; n < 16; n++) {
                of[n][0] *= a0; of[n][1] *= a0;
                of[n][2] *= a1; of[n][3] *= a1;
            }

            const int base = lane & ~3;
            const int hsrc = base + (tg >> 1);
            const bool par = (tg & 1);
#pragma unroll
            for (int kc = 0; kc < 8; kc++) {
                uint32_t a[4];
                {
                    float lo = __shfl_sync(0xffffffffu, sacc[kc][0], hsrc);
                    float hi = __shfl_sync(0xffffffffu, sacc[kc][1], hsrc);
                    a[0] = __float_as_uint(par ? hi : lo);
                    lo = __shfl_sync(0xffffffffu, sacc[kc][2], hsrc);
                    hi = __shfl_sync(0xffffffffu, sacc[kc][3], hsrc);
                    a[1] = __float_as_uint(par ? hi : lo);
                    lo = __shfl_sync(0xffffffffu, sacc[kc][0], hsrc + 2);
                    hi = __shfl_sync(0xffffffffu, sacc[kc][1], hsrc + 2);
                    a[2] = __float_as_uint(par ? hi : lo);
                    lo = __shfl_sync(0xffffffffu, sacc[kc][2], hsrc + 2);
                    hi = __shfl_sync(0xffffffffu, sacc[kc][3], hsrc + 2);
                    a[3] = __float_as_uint(par ? hi : lo);
                }
#pragma unroll
                for (int n = 0; n < 16; n++) {
                    float2 vv = sV2[(kc * 16 + n) * 32 + vOff];
                    uint32_t bf[2] = { __float_as_uint(vv.x), __float_as_uint(vv.y) };
                    mma_tf32(of[n], a, bf);
                }
            }
        }
        __syncthreads();
    }

    // epilogue: normalize + write fp16 Y (feeds fp16 FC2)
    const int b = bh >> 4, h = bh & 15;
    const float inv0 = 1.0f / l0;
    const float inv1 = 1.0f / l1;
    const int t0 = qt * 128 + wm + g;
    const int t1 = t0 + 8;
#pragma unroll
    for (int n = 0; n < 16; n++) {
        int d = 8 * n + 2 * tg;
        __half2 h0 = __floats2half2_rn(of[n][0] * inv0, of[n][1] * inv0);
        __half2 h1 = __floats2half2_rn(of[n][2] * inv1, of[n][3] * inv1);
        *(__half2*)&Y[((size_t)(b * L_ + t0)) * H_ + h * HD_ + d] = h0;
        *(__half2*)&Y[((size_t)(b * L_ + t1)) * H_ + h * HD_ + d] = h1;
    }
}

// ---------------- launcher ----------------------------------------------------
extern "C" void kernel_launch(void* const* d_in, const int* in_sizes, int n_in,
                              void* d_out, int out_size)
{
    const float* x    = (const float*)d_in[0];
    const float* Wqkv = (const float*)d_in[1];
    const float* bqkv = (const float*)d_in[2];
    const float* Wfc2 = (const float*)d_in[3];
    const float* bfc2 = (const float*)d_in[4];
    const float* cosb = (const float*)d_in[5];
    const float* sinb = (const float*)d_in[6];
    float* out = (float*)d_out;

    float *qkv, *Qh, *Kh, *Vh;
    __half *Xh, *WqT, *WfT, *Yh;
    cudaGetSymbolAddress((void**)&qkv, g_qkv);
    cudaGetSymbolAddress((void**)&Qh,  g_Q);
    cudaGetSymbolAddress((void**)&Kh,  g_K);
    cudaGetSymbolAddress((void**)&Vh,  g_V);
    cudaGetSymbolAddress((void**)&Xh,  g_Xh);
    cudaGetSymbolAddress((void**)&WqT, g_WqTh);
    cudaGetSymbolAddress((void**)&WfT, g_WfTh);
    cudaGetSymbolAddress((void**)&Yh,  g_Yh);

    cudaFuncSetAttribute(gemm_f16, cudaFuncAttributeMaxDynamicSharedMemorySize, FGEMM_SMEM);
    cudaFuncSetAttribute(attn_tc3, cudaFuncAttributeMaxDynamicSharedMemorySize, ATTN_SMEM);

    // 0) convert x -> fp16; transpose+convert weights -> fp16 [N][K]
    {
        int n4x = (int)((size_t)M_ * H_ / 4);
        f32_to_f16<<<(n4x + 255) / 256, 256>>>((const float4*)x, (uint2*)Xh, n4x);
        transpose_f16<<<dim3(N3_ / 32, H_ / 32), 256>>>(Wqkv, WqT, H_, N3_);
        transpose_f16<<<dim3(H_ / 32, H_ / 32), 256>>>(Wfc2, WfT, H_, H_);
    }

    // 1) QKV GEMM (fp16 operands, fp32 accum)
    gemm_f16<<<dim3(N3_ / FBN, M_ / FBM), 256, FGEMM_SMEM>>>(Xh, WqT, bqkv, qkv, M_, N3_, H_, 0);

    // 2) RoPE + scatter
    rope_scatter<<<M_, 256>>>(qkv, cosb, sinb, Qh, Kh, Vh);

    // 3) causal flash attention (tf32, unchanged)
    attn_tc3<<<dim3(L_ / 128, B_ * NH_), 256, ATTN_SMEM>>>(Qh, Kh, Vh, Yh);

    // 4) FC2 GEMM + SiLU (fp16 operands)
    gemm_f16<<<dim3(H_ / FBN, M_ / FBM), 256, FGEMM_SMEM>>>(Yh, WfT, bfc2, out, M_, H_, H_, 1);
}